// round 11
// baseline (speedup 1.0000x reference)
#include <cuda_runtime.h>

#define NQ  10
#define DIM 1024
#define NL  4
#define TPB 64

typedef unsigned long long u64;

// Hardcoded GF(2) swizzle matrices (fixed CNOT rings; rank-5 verified store+gather).
#define A0_0 1u
#define A0_1 2u
#define A0_2 4u
#define A0_3 9u
#define A0_4 0u
#define A1_0 2u
#define A1_1 4u
#define A1_2 8u
#define A1_3 0x11u
#define A1_4 1u
#define PC0  0x200u
#define PC1  0x201u

__device__ u64 g_gmat[NL * NQ][8];       // packed gate coefficients
__device__ unsigned g_T[2][512];         // gather word-table

__device__ __forceinline__ unsigned amul(int p, unsigned v) {
    unsigned r = 0;
    if (p == 0) {
        if (v & 1u)  r ^= A0_0;
        if (v & 2u)  r ^= A0_1;
        if (v & 4u)  r ^= A0_2;
        if (v & 8u)  r ^= A0_3;
        if (v & 16u) r ^= A0_4;
    } else {
        if (v & 1u)  r ^= A1_0;
        if (v & 2u)  r ^= A1_1;
        if (v & 4u)  r ^= A1_2;
        if (v & 8u)  r ^= A1_3;
        if (v & 16u) r ^= A1_4;
    }
    return r;
}

__device__ __forceinline__ u64 pack2(float x, float y) {
    u64 r; asm("mov.b64 %0, {%1,%2};" : "=l"(r) : "f"(x), "f"(y)); return r;
}
__device__ __forceinline__ void unpk(u64 v, float& x, float& y) {
    asm("mov.b64 {%0,%1}, %2;" : "=f"(x), "=f"(y) : "l"(v));
}
__device__ __forceinline__ u64 swp(u64 v) {
    u64 r;
    asm("{\n\t.reg .b32 lo, hi;\n\tmov.b64 {lo,hi}, %1;\n\tmov.b64 %0, {hi,lo};\n\t}"
        : "=l"(r) : "l"(v));
    return r;
}
__device__ __forceinline__ u64 ffma2(u64 a, u64 b, u64 c) {
    u64 d; asm("fma.rn.f32x2 %0, %1, %2, %3;" : "=l"(d) : "l"(a), "l"(b), "l"(c)); return d;
}
__device__ __forceinline__ u64 fmul2(u64 a, u64 b) {
    u64 d; asm("mul.rn.f32x2 %0, %1, %2;" : "=l"(d) : "l"(a), "l"(b)); return d;
}
__device__ __forceinline__ u64 fadd2(u64 a, u64 b) {
    u64 d; asm("add.rn.f32x2 %0, %1, %2;" : "=l"(d) : "l"(a), "l"(b)); return d;
}
__device__ __forceinline__ float2 cmulf(float2 a, float2 b) {
    return make_float2(a.x * b.x - a.y * b.y, a.x * b.y + a.y * b.x);
}

__device__ __forceinline__ unsigned finv10(int type, unsigned idx) {
    int off = type ? (NQ / 2) : 1;
    unsigned y = idx;
    #pragma unroll
    for (int i = NQ - 1; i >= 0; --i) {
        int bc = NQ - 1 - i;
        int bt = NQ - 1 - ((i + off) % NQ);
        y ^= ((y >> bc) & 1u) << bt;
    }
    return y;
}

__global__ void precompute_kernel(const float* __restrict__ w) {
    int t = threadIdx.x;

    if (t < NL * NQ) {
        int q = t % NQ;
        float w0 = w[t * 3 + 0], w1 = w[t * 3 + 1], w2 = w[t * 3 + 2];
        float sb, cb; sincosf(0.5f * w1, &sb, &cb);
        u64* g = g_gmat[t];
        if (q >= 1 && q <= 5) {
            float s0, c0; sincosf(0.5f * w0, &s0, &c0);   // pre  = e^{-i w0/2}
            float s2, c2; sincosf(0.5f * w2, &s2, &c2);   // post = e^{-i w2/2}
            g[0] = pack2(cb, cb);
            g[1] = pack2(sb, sb);
            g[2] = pack2(-sb, -sb);
            g[3] = pack2(c0, -s0);
            g[4] = pack2(c2, -s2);
            g[5] = 0; g[6] = 0; g[7] = 0;
        } else {
            float sp, cp; sincosf(0.5f * (w0 + w2), &sp, &cp);
            float sd, cd; sincosf(0.5f * (w0 - w2), &sd, &cd);
            float ar = cb * cp, ai = -cb * sp;   // U00
            float br = sb * cd, bi = -sb * sd;   // U10 ; U01=-conj(U10), U11=conj(U00)
            if (q == 0) {
                // merged-gather layout: {c00,d00,c01,d01, c11,d11,c10,d10}
                g[0] = pack2(ar, ar);   g[1] = pack2(-ai, ai);
                g[2] = pack2(-br, -br); g[3] = pack2(-bi, bi);
                g[4] = pack2(ar, ar);   g[5] = pack2(ai, -ai);
                g[6] = pack2(br, br);   g[7] = pack2(-bi, bi);
            } else {
                // standard layout: {c00,d00,c01,d01,c10,d10,c11,d11}
                g[0] = pack2(ar, ar);   g[1] = pack2(-ai, ai);
                g[2] = pack2(-br, -br); g[3] = pack2(-bi, bi);
                g[4] = pack2(br, br);   g[5] = pack2(-bi, bi);
                g[6] = pack2(ar, ar);   g[7] = pack2(ai, -ai);
            }
        }
    }

    // gather word-table (identical to R9)
    for (int i = t; i < 2 * 512; i += blockDim.x) {
        int p = i >> 9, widx = i & 511;
        int W = widx >> 8, lane = (widx >> 3) & 31, cs = widx & 7;
        int c = cs ^ (lane >> 2);
        unsigned j0 = (unsigned)(W * 512 + lane * 16 + 2 * c);
        unsigned e[2];
        #pragma unroll
        for (int h = 0; h < 2; ++h) {
            unsigned y = finv10(p, j0 + h);
            unsigned yh = y >> 5;
            unsigned addr = yh * 32 + ((y & 31u) ^ amul(p, yh));
            e[h] = addr | ((y >> 9) << 15);
        }
        g_T[p][widx] = e[0] | (e[1] << 16);
    }
}

// full-complex gate on k-bit mask M over 16 packed-complex amps
template<int M>
__device__ __forceinline__ void gate_reg(u64* r, const u64* __restrict__ C) {
    const u64 c00 = __ldg(C + 0), d00 = __ldg(C + 1), c01 = __ldg(C + 2), d01 = __ldg(C + 3);
    const u64 c10 = __ldg(C + 4), d10 = __ldg(C + 5), c11 = __ldg(C + 6), d11 = __ldg(C + 7);
    #pragma unroll
    for (int k = 0; k < 16; ++k) {
        if ((k & M) == 0) {
            const int k1 = k | M;
            u64 a0 = r[k], a1 = r[k1];
            u64 s0 = swp(a0), s1 = swp(a1);
            r[k]  = ffma2(c00, a0, ffma2(d00, s0, ffma2(c01, a1, fmul2(d01, s1))));
            r[k1] = ffma2(c10, a0, ffma2(d10, s0, ffma2(c11, a1, fmul2(d11, s1))));
        }
    }
}

// real RY butterfly on lane-bit xor distance D: r = c*own ± s*par
template<int D>
__device__ __forceinline__ void ry_shfl(u64* r, u64 cc, u64 ss) {
    #pragma unroll
    for (int k = 0; k < 16; ++k) {
        u64 own = r[k];
        u64 par = __shfl_xor_sync(0xffffffffu, own, D);
        r[k] = ffma2(ss, par, fmul2(cc, own));
    }
}

__global__ __launch_bounds__(TPB, 16) void qsim_kernel(
    const float* __restrict__ x,     // (B, 2*NQ)
    float* __restrict__ out)         // (B, NQ)
{
    __shared__ u64 sc[DIM];                    // 8 KB state scratch (A-swizzled)
    __shared__ unsigned Tp_s[2][512];          // 4 KB
    __shared__ float2 venc[NQ][2];
    __shared__ float red[2][NQ];

    const int t    = threadIdx.x;
    const int lane = t & 31;
    const int w    = t >> 5;                   // warp half = qubit-0 bit (j9)
    const int s    = blockIdx.x;
    const float inv_sqrt2 = 0.70710678118654752440f;
    const float pi_f      = 3.14159265358979323846f;

    // copy gather tables to smem (gate coeffs stay in global: uniform, L1/L2-resident)
    {
        const unsigned* ts = &g_T[0][0];
        unsigned* td = &Tp_s[0][0];
        for (int i = t; i < 1024; i += TPB) td[i] = ts[i];
    }
    // per-thread address constants (A hardcoded)
    const unsigned jhi = (unsigned)(w * 16 + (lane >> 1));
    const unsigned addrC0 = (jhi << 5) | (((unsigned)(lane & 1) << 4) ^ amul(0, jhi));
    const unsigned addrC1 = (jhi << 5) | (((unsigned)(lane & 1) << 4) ^ amul(1, jhi));

    if (t < NQ) {
        int q = t;
        float th = 0.5f * pi_f * (x[s * 2 * NQ + q]      + 1.0f);
        float ph = 0.5f * pi_f * (x[s * 2 * NQ + NQ + q] + 1.0f);
        float st, ct; sincosf(0.5f * th, &st, &ct);
        float sh, ch; sincosf(0.5f * ph, &sh, &ch);
        float a = inv_sqrt2 * (ct - st);
        float b = inv_sqrt2 * (ct + st);
        venc[q][0] = make_float2(a * ch, -a * sh);
        venc[q][1] = make_float2(b * ch,  b * sh);
    }
    __syncthreads();

    // ---- build product state: j = w*512 + lane*16 + k ; qubit q <-> j bit (9-q) ----
    u64 r[16];
    {
        float2 L = venc[0][w];
        L = cmulf(L, venc[1][(lane >> 4) & 1]);
        L = cmulf(L, venc[2][(lane >> 3) & 1]);
        L = cmulf(L, venc[3][(lane >> 2) & 1]);
        L = cmulf(L, venc[4][(lane >> 1) & 1]);
        L = cmulf(L, venc[5][lane & 1]);
        float2 RH[4], RL[4];
        #pragma unroll
        for (int h = 0; h < 4; ++h) RH[h] = cmulf(venc[6][(h >> 1) & 1], venc[7][h & 1]);
        #pragma unroll
        for (int l = 0; l < 4; ++l) RL[l] = cmulf(venc[8][(l >> 1) & 1], venc[9][l & 1]);
        #pragma unroll
        for (int k = 0; k < 16; ++k) {
            float2 a = cmulf(L, cmulf(RH[k >> 2], RL[k & 3]));
            r[k] = pack2(a.x, a.y);
        }
    }

    #pragma unroll 1
    for (int layer = 0; layer < NL; ++layer) {
        const u64 (*G)[8] = &g_gmat[layer * NQ];
        const int par = layer & 1;
        // qubits 6..9: full complex gates on k bits
        gate_reg<8>(r, G[6]);
        gate_reg<4>(r, G[7]);
        gate_reg<2>(r, G[8]);
        gate_reg<1>(r, G[9]);

        // ---- qubits 1..5 diagonalized: pre-phase, 5 real-RY butterflies, post-phase ----
        float2 pre = make_float2(1.0f, 0.0f), post = make_float2(1.0f, 0.0f);
        #pragma unroll
        for (int q = 1; q <= 5; ++q) {
            float px, py, ox, oy;
            unpk(__ldg(&G[q][3]), px, py);
            unpk(__ldg(&G[q][4]), ox, oy);
            if ((lane >> (5 - q)) & 1) { py = -py; oy = -oy; }
            pre  = cmulf(pre,  make_float2(px, py));
            post = cmulf(post, make_float2(ox, oy));
        }
        {
            const u64 Cp = pack2(pre.x, pre.x), Dp = pack2(-pre.y, pre.y);
            #pragma unroll
            for (int k = 0; k < 16; ++k)
                r[k] = ffma2(Cp, r[k], fmul2(Dp, swp(r[k])));
        }
        ry_shfl<16>(r, __ldg(&G[1][0]), (lane & 16) ? __ldg(&G[1][1]) : __ldg(&G[1][2]));
        ry_shfl<8>(r, __ldg(&G[2][0]), (lane & 8)  ? __ldg(&G[2][1]) : __ldg(&G[2][2]));
        ry_shfl<4>(r, __ldg(&G[3][0]), (lane & 4)  ? __ldg(&G[3][1]) : __ldg(&G[3][2]));
        ry_shfl<2>(r, __ldg(&G[4][0]), (lane & 2)  ? __ldg(&G[4][1]) : __ldg(&G[4][2]));
        ry_shfl<1>(r, __ldg(&G[5][0]), (lane & 1)  ? __ldg(&G[5][1]) : __ldg(&G[5][2]));
        if (layer < NL - 1) {
            // final layer's post-phase is a unit-modulus diagonal, constant across each
            // q0 gather pair -> invisible to the |amp|^2 readout; skip it there.
            const u64 Cq = pack2(post.x, post.x), Dq = pack2(-post.y, post.y);
            #pragma unroll
            for (int k = 0; k < 16; ++k)
                r[k] = ffma2(Cq, r[k], fmul2(Dq, swp(r[k])));
        }

        // store state (A-swizzled, conflict-free)
        const unsigned addrC = par ? addrC1 : addrC0;
        #pragma unroll
        for (int k = 0; k < 16; ++k)
            sc[addrC ^ (unsigned)k] = r[k];
        __syncthreads();
        // gather = CNOT ring composed with full qubit-0 gate (conflict-free loads)
        const unsigned PC = par ? PC1 : PC0;
        const u64 q0_0 = __ldg(&G[0][0]), q0_1 = __ldg(&G[0][1]);
        const u64 q0_2 = __ldg(&G[0][2]), q0_3 = __ldg(&G[0][3]);
        const u64 q1_0 = __ldg(&G[0][4]), q1_1 = __ldg(&G[0][5]);
        const u64 q1_2 = __ldg(&G[0][6]), q1_3 = __ldg(&G[0][7]);
        const unsigned tbase = ((unsigned)w << 8) | ((unsigned)lane << 3);
        #pragma unroll
        for (int c = 0; c < 8; ++c) {
            unsigned tw = Tp_s[par][tbase | ((unsigned)c ^ (unsigned)(lane >> 2))];
            #pragma unroll
            for (int h = 0; h < 2; ++h) {
                unsigned e = (h == 0) ? (tw & 0xffffu) : (tw >> 16);
                unsigned idx = e & 1023u;
                bool bb = (e >> 15) != 0;
                u64 a = sc[idx];
                u64 p = sc[idx ^ PC];
                u64 cA = bb ? q1_0 : q0_0;
                u64 dA = bb ? q1_1 : q0_1;
                u64 cB = bb ? q1_2 : q0_2;
                u64 dB = bb ? q1_3 : q0_3;
                r[2 * c + h] = ffma2(cA, a, ffma2(dA, swp(a), ffma2(cB, p, fmul2(dB, swp(p)))));
            }
        }
        __syncthreads();
    }

    // ---- <Z_q> readout ----
    u64 tot = 0, accP[4] = {0,0,0,0}, accN[4] = {0,0,0,0};
    #pragma unroll
    for (int k = 0; k < 16; ++k) {
        u64 sq = fmul2(r[k], r[k]);          // (re^2, im^2)
        tot = fadd2(tot, sq);
        #pragma unroll
        for (int b = 0; b < 4; ++b) {
            if ((k >> b) & 1) accN[b] = fadd2(accN[b], sq);
            else              accP[b] = fadd2(accP[b], sq);
        }
    }
    float zq[NQ];
    {
        float tl, th; unpk(tot, tl, th);
        float pr_tot = tl + th;
        zq[0] = w ? -pr_tot : pr_tot;
        zq[1] = (lane & 16) ? -pr_tot : pr_tot;
        zq[2] = (lane & 8)  ? -pr_tot : pr_tot;
        zq[3] = (lane & 4)  ? -pr_tot : pr_tot;
        zq[4] = (lane & 2)  ? -pr_tot : pr_tot;
        zq[5] = (lane & 1)  ? -pr_tot : pr_tot;
        #pragma unroll
        for (int b = 0; b < 4; ++b) {        // k bit b <-> qubit 9-b
            float pl, ph, nl, nh;
            unpk(accP[b], pl, ph); unpk(accN[b], nl, nh);
            zq[9 - b] = (pl + ph) - (nl + nh);
        }
    }
    #pragma unroll
    for (int q = 0; q < NQ; ++q) {
        #pragma unroll
        for (int o = 16; o > 0; o >>= 1)
            zq[q] += __shfl_xor_sync(0xffffffffu, zq[q], o);
    }
    if (lane == 0) {
        #pragma unroll
        for (int q = 0; q < NQ; ++q) red[w][q] = zq[q];
    }
    __syncthreads();
    if (t < NQ)
        out[s * NQ + t] = red[0][t] + red[1][t];
}

extern "C" void kernel_launch(void* const* d_in, const int* in_sizes, int n_in,
                              void* d_out, int out_size) {
    const float* x = (const float*)d_in[0];
    const float* w = (const float*)d_in[1];
    float* out = (float*)d_out;
    int B = in_sizes[0] / (2 * NQ);   // 4096 flattened samples
    precompute_kernel<<<1, 128>>>(w);
    qsim_kernel<<<B, TPB>>>(x, out);
}

// round 12
// speedup vs baseline: 1.2827x; 1.2827x over previous
#include <cuda_runtime.h>

#define NQ  10
#define DIM 1024
#define NL  4
#define TPB 64

typedef unsigned long long u64;

// Hardcoded GF(2) swizzle matrices (fixed CNOT rings; rank-5 verified store+gather).
#define A0_0 1u
#define A0_1 2u
#define A0_2 4u
#define A0_3 9u
#define A0_4 0u
#define A1_0 2u
#define A1_1 4u
#define A1_2 8u
#define A1_3 0x11u
#define A1_4 1u
#define PC0  0x200u
#define PC1  0x201u

__device__ u64 g_gmat[NL * NQ][8];       // packed gate coefficients
__device__ unsigned g_T[2][512];         // gather word-table
__device__ u64 g_pre[NL][32][2];         // per-(layer,lane) pre-phase packs (C,D)
__device__ u64 g_post[NL][32][2];        // per-(layer,lane) post-phase packs (C,D)

__device__ __forceinline__ unsigned amul(int p, unsigned v) {
    unsigned r = 0;
    if (p == 0) {
        if (v & 1u)  r ^= A0_0;
        if (v & 2u)  r ^= A0_1;
        if (v & 4u)  r ^= A0_2;
        if (v & 8u)  r ^= A0_3;
        if (v & 16u) r ^= A0_4;
    } else {
        if (v & 1u)  r ^= A1_0;
        if (v & 2u)  r ^= A1_1;
        if (v & 4u)  r ^= A1_2;
        if (v & 8u)  r ^= A1_3;
        if (v & 16u) r ^= A1_4;
    }
    return r;
}

__device__ __forceinline__ u64 pack2(float x, float y) {
    u64 r; asm("mov.b64 %0, {%1,%2};" : "=l"(r) : "f"(x), "f"(y)); return r;
}
__device__ __forceinline__ void unpk(u64 v, float& x, float& y) {
    asm("mov.b64 {%0,%1}, %2;" : "=f"(x), "=f"(y) : "l"(v));
}
__device__ __forceinline__ u64 swp(u64 v) {
    u64 r;
    asm("{\n\t.reg .b32 lo, hi;\n\tmov.b64 {lo,hi}, %1;\n\tmov.b64 %0, {hi,lo};\n\t}"
        : "=l"(r) : "l"(v));
    return r;
}
__device__ __forceinline__ u64 ffma2(u64 a, u64 b, u64 c) {
    u64 d; asm("fma.rn.f32x2 %0, %1, %2, %3;" : "=l"(d) : "l"(a), "l"(b), "l"(c)); return d;
}
__device__ __forceinline__ u64 fmul2(u64 a, u64 b) {
    u64 d; asm("mul.rn.f32x2 %0, %1, %2;" : "=l"(d) : "l"(a), "l"(b)); return d;
}
__device__ __forceinline__ u64 fadd2(u64 a, u64 b) {
    u64 d; asm("add.rn.f32x2 %0, %1, %2;" : "=l"(d) : "l"(a), "l"(b)); return d;
}
__device__ __forceinline__ float2 cmulf(float2 a, float2 b) {
    return make_float2(a.x * b.x - a.y * b.y, a.x * b.y + a.y * b.x);
}

__device__ __forceinline__ unsigned finv10(int type, unsigned idx) {
    int off = type ? (NQ / 2) : 1;
    unsigned y = idx;
    #pragma unroll
    for (int i = NQ - 1; i >= 0; --i) {
        int bc = NQ - 1 - i;
        int bt = NQ - 1 - ((i + off) % NQ);
        y ^= ((y >> bc) & 1u) << bt;
    }
    return y;
}

__global__ void precompute_kernel(const float* __restrict__ w) {
    int t = threadIdx.x;

    // fused variational gates
    if (t < NL * NQ) {
        int q = t % NQ;
        float w0 = w[t * 3 + 0], w1 = w[t * 3 + 1], w2 = w[t * 3 + 2];
        float sb, cb; sincosf(0.5f * w1, &sb, &cb);
        u64* g = g_gmat[t];
        if (q >= 1 && q <= 5) {
            g[0] = pack2(cb, cb);
            g[1] = pack2(sb, sb);
            g[2] = pack2(-sb, -sb);
            g[3] = 0; g[4] = 0; g[5] = 0; g[6] = 0; g[7] = 0;
        } else {
            float sp, cp; sincosf(0.5f * (w0 + w2), &sp, &cp);
            float sd, cd; sincosf(0.5f * (w0 - w2), &sd, &cd);
            float ar = cb * cp, ai = -cb * sp;   // U00
            float br = sb * cd, bi = -sb * sd;   // U10 ; U01=-conj(U10), U11=conj(U00)
            if (q == 0) {
                // merged-gather layout: {c00,d00,c01,d01, c11,d11,c10,d10}
                g[0] = pack2(ar, ar);   g[1] = pack2(-ai, ai);
                g[2] = pack2(-br, -br); g[3] = pack2(-bi, bi);
                g[4] = pack2(ar, ar);   g[5] = pack2(ai, -ai);
                g[6] = pack2(br, br);   g[7] = pack2(-bi, bi);
            } else {
                // standard layout: {c00,d00,c01,d01,c10,d10,c11,d11}
                g[0] = pack2(ar, ar);   g[1] = pack2(-ai, ai);
                g[2] = pack2(-br, -br); g[3] = pack2(-bi, bi);
                g[4] = pack2(br, br);   g[5] = pack2(-bi, bi);
                g[6] = pack2(ar, ar);   g[7] = pack2(ai, -ai);
            }
        }
    }

    // per-(layer,lane) pre/post phase scalar packs (128 threads = NL*32 exactly)
    {
        int l = t >> 5, lane = t & 31;
        float2 pre = make_float2(1.0f, 0.0f), post = make_float2(1.0f, 0.0f);
        #pragma unroll
        for (int q = 1; q <= 5; ++q) {
            float w0 = w[(l * NQ + q) * 3 + 0];
            float w2 = w[(l * NQ + q) * 3 + 2];
            float s0, c0; sincosf(0.5f * w0, &s0, &c0);
            float s2, c2; sincosf(0.5f * w2, &s2, &c2);
            float py = -s0, oy = -s2;
            if ((lane >> (5 - q)) & 1) { py = -py; oy = -oy; }
            pre  = cmulf(pre,  make_float2(c0, py));
            post = cmulf(post, make_float2(c2, oy));
        }
        g_pre[l][lane][0]  = pack2(pre.x, pre.x);
        g_pre[l][lane][1]  = pack2(-pre.y, pre.y);
        g_post[l][lane][0] = pack2(post.x, post.x);
        g_post[l][lane][1] = pack2(-post.y, post.y);
    }

    // gather word-table (identical to R9)
    for (int i = t; i < 2 * 512; i += blockDim.x) {
        int p = i >> 9, widx = i & 511;
        int W = widx >> 8, lane = (widx >> 3) & 31, cs = widx & 7;
        int c = cs ^ (lane >> 2);
        unsigned j0 = (unsigned)(W * 512 + lane * 16 + 2 * c);
        unsigned e[2];
        #pragma unroll
        for (int h = 0; h < 2; ++h) {
            unsigned y = finv10(p, j0 + h);
            unsigned yh = y >> 5;
            unsigned addr = yh * 32 + ((y & 31u) ^ amul(p, yh));
            e[h] = addr | ((y >> 9) << 15);
        }
        g_T[p][widx] = e[0] | (e[1] << 16);
    }
}

// full-complex gate on k-bit mask M over 16 packed-complex amps
template<int M>
__device__ __forceinline__ void gate_reg(u64* r, const u64* __restrict__ C) {
    const u64 c00 = C[0], d00 = C[1], c01 = C[2], d01 = C[3];
    const u64 c10 = C[4], d10 = C[5], c11 = C[6], d11 = C[7];
    #pragma unroll
    for (int k = 0; k < 16; ++k) {
        if ((k & M) == 0) {
            const int k1 = k | M;
            u64 a0 = r[k], a1 = r[k1];
            u64 s0 = swp(a0), s1 = swp(a1);
            r[k]  = ffma2(c00, a0, ffma2(d00, s0, ffma2(c01, a1, fmul2(d01, s1))));
            r[k1] = ffma2(c10, a0, ffma2(d10, s0, ffma2(c11, a1, fmul2(d11, s1))));
        }
    }
}

// real RY butterfly on lane-bit xor distance D: r = c*own ± s*par
template<int D>
__device__ __forceinline__ void ry_shfl(u64* r, u64 cc, u64 ss) {
    #pragma unroll
    for (int k = 0; k < 16; ++k) {
        u64 own = r[k];
        u64 par = __shfl_xor_sync(0xffffffffu, own, D);
        r[k] = ffma2(ss, par, fmul2(cc, own));
    }
}

// per-thread diagonal phase pass from (C,D) packs
__device__ __forceinline__ void phase_pass(u64* r, u64 C, u64 D) {
    #pragma unroll
    for (int k = 0; k < 16; ++k)
        r[k] = ffma2(C, r[k], fmul2(D, swp(r[k])));
}

__global__ __launch_bounds__(TPB, 12) void qsim_kernel(
    const float* __restrict__ x,     // (B, 2*NQ)
    float* __restrict__ out)         // (B, NQ)
{
    __shared__ u64 sc[DIM];                    // 8 KB state scratch (A-swizzled)
    __shared__ u64 gmat_s[NL * NQ][8];         // 2.5 KB
    __shared__ unsigned Tp_s[2][512];          // 4 KB
    __shared__ u64 pp_s[NL][32][4];            // 4 KB: {preC,preD,postC,postD}
    __shared__ float2 venc[NQ][2];
    __shared__ float red[2][NQ];

    const int t    = threadIdx.x;
    const int lane = t & 31;
    const int w    = t >> 5;                   // warp half = qubit-0 bit (j9)
    const int s    = blockIdx.x;
    const float inv_sqrt2 = 0.70710678118654752440f;
    const float pi_f      = 3.14159265358979323846f;

    // copy precomputed tables to smem
    {
        const u64* src = &g_gmat[0][0];
        u64* dst = &gmat_s[0][0];
        for (int i = t; i < NL * NQ * 8; i += TPB) dst[i] = src[i];
        const unsigned* ts = &g_T[0][0];
        unsigned* td = &Tp_s[0][0];
        for (int i = t; i < 1024; i += TPB) td[i] = ts[i];
        // phase packs: thread t covers 2 entries (NL*32*4 = 512 u64 / 64 threads = 8)
        const u64* ps = &g_pre[0][0][0];
        const u64* qs = &g_post[0][0][0];
        for (int i = t; i < NL * 32; i += TPB) {
            int l = i >> 5, ln = i & 31;
            pp_s[l][ln][0] = ps[i * 2 + 0];
            pp_s[l][ln][1] = ps[i * 2 + 1];
            pp_s[l][ln][2] = qs[i * 2 + 0];
            pp_s[l][ln][3] = qs[i * 2 + 1];
        }
    }
    // per-thread address constants (A hardcoded)
    const unsigned jhi = (unsigned)(w * 16 + (lane >> 1));
    const unsigned addrC0 = (jhi << 5) | (((unsigned)(lane & 1) << 4) ^ amul(0, jhi));
    const unsigned addrC1 = (jhi << 5) | (((unsigned)(lane & 1) << 4) ^ amul(1, jhi));

    if (t < NQ) {
        int q = t;
        float th = 0.5f * pi_f * (x[s * 2 * NQ + q]      + 1.0f);
        float ph = 0.5f * pi_f * (x[s * 2 * NQ + NQ + q] + 1.0f);
        float st, ct; sincosf(0.5f * th, &st, &ct);
        float sh, ch; sincosf(0.5f * ph, &sh, &ch);
        float a = inv_sqrt2 * (ct - st);
        float b = inv_sqrt2 * (ct + st);
        venc[q][0] = make_float2(a * ch, -a * sh);
        venc[q][1] = make_float2(b * ch,  b * sh);
    }
    __syncthreads();

    // ---- build product state: j = w*512 + lane*16 + k ; qubit q <-> j bit (9-q) ----
    u64 r[16];
    {
        float2 L = venc[0][w];
        L = cmulf(L, venc[1][(lane >> 4) & 1]);
        L = cmulf(L, venc[2][(lane >> 3) & 1]);
        L = cmulf(L, venc[3][(lane >> 2) & 1]);
        L = cmulf(L, venc[4][(lane >> 1) & 1]);
        L = cmulf(L, venc[5][lane & 1]);
        float2 RH[4], RL[4];
        #pragma unroll
        for (int h = 0; h < 4; ++h) RH[h] = cmulf(venc[6][(h >> 1) & 1], venc[7][h & 1]);
        #pragma unroll
        for (int l = 0; l < 4; ++l) RL[l] = cmulf(venc[8][(l >> 1) & 1], venc[9][l & 1]);
        #pragma unroll
        for (int k = 0; k < 16; ++k) {
            float2 a = cmulf(L, cmulf(RH[k >> 2], RL[k & 3]));
            r[k] = pack2(a.x, a.y);
        }
    }

    #pragma unroll 1
    for (int layer = 0; layer < NL; ++layer) {
        const u64 (*G)[8] = &gmat_s[layer * NQ];
        const int par = layer & 1;
        // qubits 6..9: full complex gates on k bits
        gate_reg<8>(r, G[6]);
        gate_reg<4>(r, G[7]);
        gate_reg<2>(r, G[8]);
        gate_reg<1>(r, G[9]);

        // ---- qubits 1..5 diagonalized: table pre-phase, 5 RY butterflies, post-phase ----
        const u64* pp = pp_s[layer][lane];
        phase_pass(r, pp[0], pp[1]);
        ry_shfl<16>(r, G[1][0], (lane & 16) ? G[1][1] : G[1][2]);
        ry_shfl<8>(r, G[2][0], (lane & 8)  ? G[2][1] : G[2][2]);
        ry_shfl<4>(r, G[3][0], (lane & 4)  ? G[3][1] : G[3][2]);
        ry_shfl<2>(r, G[4][0], (lane & 2)  ? G[4][1] : G[4][2]);
        ry_shfl<1>(r, G[5][0], (lane & 1)  ? G[5][1] : G[5][2]);
        if (layer < NL - 1) {
            // final layer's post-phase is unit-modulus and constant across each q0
            // gather pair -> invisible to |amp|^2 readout; skip it there.
            phase_pass(r, pp[2], pp[3]);
        }

        // store state (A-swizzled, conflict-free)
        const unsigned addrC = par ? addrC1 : addrC0;
        #pragma unroll
        for (int k = 0; k < 16; ++k)
            sc[addrC ^ (unsigned)k] = r[k];
        __syncthreads();
        // gather = CNOT ring composed with full qubit-0 gate (conflict-free loads)
        const unsigned PC = par ? PC1 : PC0;
        const u64 q0_0 = G[0][0], q0_1 = G[0][1], q0_2 = G[0][2], q0_3 = G[0][3];
        const u64 q1_0 = G[0][4], q1_1 = G[0][5], q1_2 = G[0][6], q1_3 = G[0][7];
        const unsigned tbase = ((unsigned)w << 8) | ((unsigned)lane << 3);
        #pragma unroll
        for (int c = 0; c < 8; ++c) {
            unsigned tw = Tp_s[par][tbase | ((unsigned)c ^ (unsigned)(lane >> 2))];
            #pragma unroll
            for (int h = 0; h < 2; ++h) {
                unsigned e = (h == 0) ? (tw & 0xffffu) : (tw >> 16);
                unsigned idx = e & 1023u;
                bool bb = (e >> 15) != 0;
                u64 a = sc[idx];
                u64 p = sc[idx ^ PC];
                u64 cA = bb ? q1_0 : q0_0;
                u64 dA = bb ? q1_1 : q0_1;
                u64 cB = bb ? q1_2 : q0_2;
                u64 dB = bb ? q1_3 : q0_3;
                r[2 * c + h] = ffma2(cA, a, ffma2(dA, swp(a), ffma2(cB, p, fmul2(dB, swp(p)))));
            }
        }
        __syncthreads();
    }

    // ---- <Z_q> readout ----
    u64 tot = 0, accP[4] = {0,0,0,0}, accN[4] = {0,0,0,0};
    #pragma unroll
    for (int k = 0; k < 16; ++k) {
        u64 sq = fmul2(r[k], r[k]);          // (re^2, im^2)
        tot = fadd2(tot, sq);
        #pragma unroll
        for (int b = 0; b < 4; ++b) {
            if ((k >> b) & 1) accN[b] = fadd2(accN[b], sq);
            else              accP[b] = fadd2(accP[b], sq);
        }
    }
    float zq[NQ];
    {
        float tl, th; unpk(tot, tl, th);
        float pr_tot = tl + th;
        zq[0] = w ? -pr_tot : pr_tot;
        zq[1] = (lane & 16) ? -pr_tot : pr_tot;
        zq[2] = (lane & 8)  ? -pr_tot : pr_tot;
        zq[3] = (lane & 4)  ? -pr_tot : pr_tot;
        zq[4] = (lane & 2)  ? -pr_tot : pr_tot;
        zq[5] = (lane & 1)  ? -pr_tot : pr_tot;
        #pragma unroll
        for (int b = 0; b < 4; ++b) {        // k bit b <-> qubit 9-b
            float pl, ph, nl, nh;
            unpk(accP[b], pl, ph); unpk(accN[b], nl, nh);
            zq[9 - b] = (pl + ph) - (nl + nh);
        }
    }
    #pragma unroll
    for (int q = 0; q < NQ; ++q) {
        #pragma unroll
        for (int o = 16; o > 0; o >>= 1)
            zq[q] += __shfl_xor_sync(0xffffffffu, zq[q], o);
    }
    if (lane == 0) {
        #pragma unroll
        for (int q = 0; q < NQ; ++q) red[w][q] = zq[q];
    }
    __syncthreads();
    if (t < NQ)
        out[s * NQ + t] = red[0][t] + red[1][t];
}

extern "C" void kernel_launch(void* const* d_in, const int* in_sizes, int n_in,
                              void* d_out, int out_size) {
    const float* x = (const float*)d_in[0];
    const float* w = (const float*)d_in[1];
    float* out = (float*)d_out;
    int B = in_sizes[0] / (2 * NQ);   // 4096 flattened samples
    precompute_kernel<<<1, 128>>>(w);
    qsim_kernel<<<B, TPB>>>(x, out);
}

// round 13
// speedup vs baseline: 1.3992x; 1.0908x over previous
#include <cuda_runtime.h>

#define NQ  10
#define DIM 1024
#define NL  4
#define TPB 64

typedef unsigned long long u64;

// Hardcoded GF(2) swizzle matrices (fixed CNOT rings; rank-5 verified store+gather).
#define A0_0 1u
#define A0_1 2u
#define A0_2 4u
#define A0_3 9u
#define A0_4 0u
#define A1_0 2u
#define A1_1 4u
#define A1_2 8u
#define A1_3 0x11u
#define A1_4 1u
#define PC0  0x200u
#define PC1  0x201u

// compact gate layout per layer (55 u64):
//   [0..7]   q0 merged-gather coeffs
//   [8+3(q-1) .. ] q1..q5: {C, Sp, Sn}
//   [23+8(q-6) .. ] q6..q9: full 8-pack
#define GL 55

__device__ __align__(16) u64 g_gmat2[NL * GL + 1];   // +1 pad -> even count for uint4 copy
__device__ __align__(16) unsigned g_T[2][512];       // gather word-table
__device__ __align__(16) u64 g_pp[NL][32][4];        // {preC,preD,postC,postD}

__device__ __forceinline__ unsigned amul(int p, unsigned v) {
    unsigned r = 0;
    if (p == 0) {
        if (v & 1u)  r ^= A0_0;
        if (v & 2u)  r ^= A0_1;
        if (v & 4u)  r ^= A0_2;
        if (v & 8u)  r ^= A0_3;
        if (v & 16u) r ^= A0_4;
    } else {
        if (v & 1u)  r ^= A1_0;
        if (v & 2u)  r ^= A1_1;
        if (v & 4u)  r ^= A1_2;
        if (v & 8u)  r ^= A1_3;
        if (v & 16u) r ^= A1_4;
    }
    return r;
}

__device__ __forceinline__ u64 pack2(float x, float y) {
    u64 r; asm("mov.b64 %0, {%1,%2};" : "=l"(r) : "f"(x), "f"(y)); return r;
}
__device__ __forceinline__ void unpk(u64 v, float& x, float& y) {
    asm("mov.b64 {%0,%1}, %2;" : "=f"(x), "=f"(y) : "l"(v));
}
__device__ __forceinline__ u64 swp(u64 v) {
    u64 r;
    asm("{\n\t.reg .b32 lo, hi;\n\tmov.b64 {lo,hi}, %1;\n\tmov.b64 %0, {hi,lo};\n\t}"
        : "=l"(r) : "l"(v));
    return r;
}
__device__ __forceinline__ u64 ffma2(u64 a, u64 b, u64 c) {
    u64 d; asm("fma.rn.f32x2 %0, %1, %2, %3;" : "=l"(d) : "l"(a), "l"(b), "l"(c)); return d;
}
__device__ __forceinline__ u64 fmul2(u64 a, u64 b) {
    u64 d; asm("mul.rn.f32x2 %0, %1, %2;" : "=l"(d) : "l"(a), "l"(b)); return d;
}
__device__ __forceinline__ u64 fadd2(u64 a, u64 b) {
    u64 d; asm("add.rn.f32x2 %0, %1, %2;" : "=l"(d) : "l"(a), "l"(b)); return d;
}
__device__ __forceinline__ float2 cmulf(float2 a, float2 b) {
    return make_float2(a.x * b.x - a.y * b.y, a.x * b.y + a.y * b.x);
}

__device__ __forceinline__ unsigned finv10(int type, unsigned idx) {
    int off = type ? (NQ / 2) : 1;
    unsigned y = idx;
    #pragma unroll
    for (int i = NQ - 1; i >= 0; --i) {
        int bc = NQ - 1 - i;
        int bt = NQ - 1 - ((i + off) % NQ);
        y ^= ((y >> bc) & 1u) << bt;
    }
    return y;
}

__global__ void precompute_kernel(const float* __restrict__ w) {
    int t = threadIdx.x;

    // fused variational gates (compact layout)
    if (t < NL * NQ) {
        int l = t / NQ, q = t % NQ;
        float w0 = w[t * 3 + 0], w1 = w[t * 3 + 1], w2 = w[t * 3 + 2];
        float sb, cb; sincosf(0.5f * w1, &sb, &cb);
        if (q >= 1 && q <= 5) {
            u64* g = &g_gmat2[l * GL + 8 + (q - 1) * 3];
            g[0] = pack2(cb, cb);
            g[1] = pack2(sb, sb);
            g[2] = pack2(-sb, -sb);
        } else {
            float sp, cp; sincosf(0.5f * (w0 + w2), &sp, &cp);
            float sd, cd; sincosf(0.5f * (w0 - w2), &sd, &cd);
            float ar = cb * cp, ai = -cb * sp;   // U00
            float br = sb * cd, bi = -sb * sd;   // U10 ; U01=-conj(U10), U11=conj(U00)
            if (q == 0) {
                u64* g = &g_gmat2[l * GL];
                // merged-gather layout: {c00,d00,c01,d01, c11,d11,c10,d10}
                g[0] = pack2(ar, ar);   g[1] = pack2(-ai, ai);
                g[2] = pack2(-br, -br); g[3] = pack2(-bi, bi);
                g[4] = pack2(ar, ar);   g[5] = pack2(ai, -ai);
                g[6] = pack2(br, br);   g[7] = pack2(-bi, bi);
            } else {
                u64* g = &g_gmat2[l * GL + 23 + (q - 6) * 8];
                // standard layout: {c00,d00,c01,d01,c10,d10,c11,d11}
                g[0] = pack2(ar, ar);   g[1] = pack2(-ai, ai);
                g[2] = pack2(-br, -br); g[3] = pack2(-bi, bi);
                g[4] = pack2(br, br);   g[5] = pack2(-bi, bi);
                g[6] = pack2(ar, ar);   g[7] = pack2(ai, -ai);
            }
        }
    }
    if (t == 0) g_gmat2[NL * GL] = 0;   // pad

    // per-(layer,lane) pre/post phase scalar packs (128 threads = NL*32 exactly)
    {
        int l = t >> 5, lane = t & 31;
        float2 pre = make_float2(1.0f, 0.0f), post = make_float2(1.0f, 0.0f);
        #pragma unroll
        for (int q = 1; q <= 5; ++q) {
            float w0 = w[(l * NQ + q) * 3 + 0];
            float w2 = w[(l * NQ + q) * 3 + 2];
            float s0, c0; sincosf(0.5f * w0, &s0, &c0);
            float s2, c2; sincosf(0.5f * w2, &s2, &c2);
            float py = -s0, oy = -s2;
            if ((lane >> (5 - q)) & 1) { py = -py; oy = -oy; }
            pre  = cmulf(pre,  make_float2(c0, py));
            post = cmulf(post, make_float2(c2, oy));
        }
        g_pp[l][lane][0] = pack2(pre.x, pre.x);
        g_pp[l][lane][1] = pack2(-pre.y, pre.y);
        g_pp[l][lane][2] = pack2(post.x, post.x);
        g_pp[l][lane][3] = pack2(-post.y, post.y);
    }

    // gather word-table (identical to R9/R12)
    for (int i = t; i < 2 * 512; i += blockDim.x) {
        int p = i >> 9, widx = i & 511;
        int W = widx >> 8, lane = (widx >> 3) & 31, cs = widx & 7;
        int c = cs ^ (lane >> 2);
        unsigned j0 = (unsigned)(W * 512 + lane * 16 + 2 * c);
        unsigned e[2];
        #pragma unroll
        for (int h = 0; h < 2; ++h) {
            unsigned y = finv10(p, j0 + h);
            unsigned yh = y >> 5;
            unsigned addr = yh * 32 + ((y & 31u) ^ amul(p, yh));
            e[h] = addr | ((y >> 9) << 15);
        }
        g_T[p][widx] = e[0] | (e[1] << 16);
    }
}

// full-complex gate on k-bit mask M over 16 packed-complex amps
template<int M>
__device__ __forceinline__ void gate_reg(u64* r, const u64* __restrict__ C) {
    const u64 c00 = C[0], d00 = C[1], c01 = C[2], d01 = C[3];
    const u64 c10 = C[4], d10 = C[5], c11 = C[6], d11 = C[7];
    #pragma unroll
    for (int k = 0; k < 16; ++k) {
        if ((k & M) == 0) {
            const int k1 = k | M;
            u64 a0 = r[k], a1 = r[k1];
            u64 s0 = swp(a0), s1 = swp(a1);
            r[k]  = ffma2(c00, a0, ffma2(d00, s0, ffma2(c01, a1, fmul2(d01, s1))));
            r[k1] = ffma2(c10, a0, ffma2(d10, s0, ffma2(c11, a1, fmul2(d11, s1))));
        }
    }
}

// real RY butterfly on lane-bit xor distance D: r = c*own ± s*par
template<int D>
__device__ __forceinline__ void ry_shfl(u64* r, u64 cc, u64 ss) {
    #pragma unroll
    for (int k = 0; k < 16; ++k) {
        u64 own = r[k];
        u64 par = __shfl_xor_sync(0xffffffffu, own, D);
        r[k] = ffma2(ss, par, fmul2(cc, own));
    }
}

// per-thread diagonal phase pass from (C,D) packs
__device__ __forceinline__ void phase_pass(u64* r, u64 C, u64 D) {
    #pragma unroll
    for (int k = 0; k < 16; ++k)
        r[k] = ffma2(C, r[k], fmul2(D, swp(r[k])));
}

__global__ __launch_bounds__(TPB, 12) void qsim_kernel(
    const float* __restrict__ x,     // (B, 2*NQ)
    float* __restrict__ out)         // (B, NQ)
{
    __shared__ __align__(16) u64 sc[DIM];             // 8 KB state scratch
    __shared__ __align__(16) u64 gmat_s[NL * GL + 1]; // 1.77 KB compact gates
    __shared__ __align__(16) unsigned Tp_s[2][512];   // 4 KB
    __shared__ __align__(16) u64 pp_s[NL][32][4];     // 4 KB
    __shared__ float2 venc[NQ][2];
    __shared__ float red[2][NQ];

    const int t    = threadIdx.x;
    const int lane = t & 31;
    const int w    = t >> 5;                   // warp half = qubit-0 bit (j9)
    const int s    = blockIdx.x;
    const float inv_sqrt2 = 0.70710678118654752440f;
    const float pi_f      = 3.14159265358979323846f;

    // vectorized table copies (uint4)
    {
        const uint4* gs = (const uint4*)&g_gmat2[0];
        uint4* gd = (uint4*)&gmat_s[0];
        #pragma unroll
        for (int i = t; i < (NL * GL + 1) / 2; i += TPB) gd[i] = gs[i];
        const uint4* ts = (const uint4*)&g_T[0][0];
        uint4* td = (uint4*)&Tp_s[0][0];
        #pragma unroll
        for (int i = t; i < 256; i += TPB) td[i] = ts[i];
        const uint4* ps = (const uint4*)&g_pp[0][0][0];
        uint4* pd = (uint4*)&pp_s[0][0][0];
        #pragma unroll
        for (int i = t; i < 256; i += TPB) pd[i] = ps[i];
    }
    // per-thread address constants (A hardcoded)
    const unsigned jhi = (unsigned)(w * 16 + (lane >> 1));
    const unsigned addrC0 = (jhi << 5) | (((unsigned)(lane & 1) << 4) ^ amul(0, jhi));
    const unsigned addrC1 = (jhi << 5) | (((unsigned)(lane & 1) << 4) ^ amul(1, jhi));

    if (t < NQ) {
        int q = t;
        float th = 0.5f * pi_f * (x[s * 2 * NQ + q]      + 1.0f);
        float ph = 0.5f * pi_f * (x[s * 2 * NQ + NQ + q] + 1.0f);
        float st, ct; sincosf(0.5f * th, &st, &ct);
        float sh, ch; sincosf(0.5f * ph, &sh, &ch);
        float a = inv_sqrt2 * (ct - st);
        float b = inv_sqrt2 * (ct + st);
        venc[q][0] = make_float2(a * ch, -a * sh);
        venc[q][1] = make_float2(b * ch,  b * sh);
    }
    __syncthreads();

    // ---- build product state: j = w*512 + lane*16 + k ; qubit q <-> j bit (9-q) ----
    u64 r[16];
    {
        float2 L = venc[0][w];
        L = cmulf(L, venc[1][(lane >> 4) & 1]);
        L = cmulf(L, venc[2][(lane >> 3) & 1]);
        L = cmulf(L, venc[3][(lane >> 2) & 1]);
        L = cmulf(L, venc[4][(lane >> 1) & 1]);
        L = cmulf(L, venc[5][lane & 1]);
        float2 RH[4], RL[4];
        #pragma unroll
        for (int h = 0; h < 4; ++h) RH[h] = cmulf(venc[6][(h >> 1) & 1], venc[7][h & 1]);
        #pragma unroll
        for (int l = 0; l < 4; ++l) RL[l] = cmulf(venc[8][(l >> 1) & 1], venc[9][l & 1]);
        #pragma unroll
        for (int k = 0; k < 16; ++k) {
            float2 a = cmulf(L, cmulf(RH[k >> 2], RL[k & 3]));
            r[k] = pack2(a.x, a.y);
        }
    }

    #pragma unroll 1
    for (int layer = 0; layer < NL; ++layer) {
        const u64* GB = &gmat_s[layer * GL];
        const int par = layer & 1;
        // qubits 6..9: full complex gates on k bits
        gate_reg<8>(r, GB + 23 + 0 * 8);
        gate_reg<4>(r, GB + 23 + 1 * 8);
        gate_reg<2>(r, GB + 23 + 2 * 8);
        gate_reg<1>(r, GB + 23 + 3 * 8);

        // ---- qubits 1..5 diagonalized: table pre-phase, 5 RY butterflies, post-phase ----
        const u64* pp = pp_s[layer][lane];
        phase_pass(r, pp[0], pp[1]);
        ry_shfl<16>(r, GB[8],  (lane & 16) ? GB[9]  : GB[10]);
        ry_shfl<8>(r, GB[11], (lane & 8)  ? GB[12] : GB[13]);
        ry_shfl<4>(r, GB[14], (lane & 4)  ? GB[15] : GB[16]);
        ry_shfl<2>(r, GB[17], (lane & 2)  ? GB[18] : GB[19]);
        ry_shfl<1>(r, GB[20], (lane & 1)  ? GB[21] : GB[22]);
        if (layer < NL - 1) {
            // final layer's post-phase is unit-modulus & per-element -> invisible to |amp|^2.
            phase_pass(r, pp[2], pp[3]);
        }

        // store state (A-swizzled, conflict-free)
        const unsigned addrC = par ? addrC1 : addrC0;
        #pragma unroll
        for (int k = 0; k < 16; ++k)
            sc[addrC ^ (unsigned)k] = r[k];
        __syncthreads();
        // gather = CNOT ring composed with full qubit-0 gate (conflict-free loads)
        const unsigned PC = par ? PC1 : PC0;
        const u64 q0_0 = GB[0], q0_1 = GB[1], q0_2 = GB[2], q0_3 = GB[3];
        const u64 q1_0 = GB[4], q1_1 = GB[5], q1_2 = GB[6], q1_3 = GB[7];
        const unsigned tbase = ((unsigned)w << 8) | ((unsigned)lane << 3);
        #pragma unroll
        for (int c = 0; c < 8; ++c) {
            unsigned tw = Tp_s[par][tbase | ((unsigned)c ^ (unsigned)(lane >> 2))];
            #pragma unroll
            for (int h = 0; h < 2; ++h) {
                unsigned e = (h == 0) ? (tw & 0xffffu) : (tw >> 16);
                unsigned idx = e & 1023u;
                bool bb = (e >> 15) != 0;
                u64 a = sc[idx];
                u64 p = sc[idx ^ PC];
                u64 cA = bb ? q1_0 : q0_0;
                u64 dA = bb ? q1_1 : q0_1;
                u64 cB = bb ? q1_2 : q0_2;
                u64 dB = bb ? q1_3 : q0_3;
                r[2 * c + h] = ffma2(cA, a, ffma2(dA, swp(a), ffma2(cB, p, fmul2(dB, swp(p)))));
            }
        }
        __syncthreads();
    }

    // ---- <Z_q> readout ----
    u64 tot = 0, accP[4] = {0,0,0,0}, accN[4] = {0,0,0,0};
    #pragma unroll
    for (int k = 0; k < 16; ++k) {
        u64 sq = fmul2(r[k], r[k]);          // (re^2, im^2)
        tot = fadd2(tot, sq);
        #pragma unroll
        for (int b = 0; b < 4; ++b) {
            if ((k >> b) & 1) accN[b] = fadd2(accN[b], sq);
            else              accP[b] = fadd2(accP[b], sq);
        }
    }
    float zq[NQ];
    {
        float tl, th; unpk(tot, tl, th);
        float pr_tot = tl + th;
        zq[0] = w ? -pr_tot : pr_tot;
        zq[1] = (lane & 16) ? -pr_tot : pr_tot;
        zq[2] = (lane & 8)  ? -pr_tot : pr_tot;
        zq[3] = (lane & 4)  ? -pr_tot : pr_tot;
        zq[4] = (lane & 2)  ? -pr_tot : pr_tot;
        zq[5] = (lane & 1)  ? -pr_tot : pr_tot;
        #pragma unroll
        for (int b = 0; b < 4; ++b) {        // k bit b <-> qubit 9-b
            float pl, ph, nl, nh;
            unpk(accP[b], pl, ph); unpk(accN[b], nl, nh);
            zq[9 - b] = (pl + ph) - (nl + nh);
        }
    }
    #pragma unroll
    for (int q = 0; q < NQ; ++q) {
        #pragma unroll
        for (int o = 16; o > 0; o >>= 1)
            zq[q] += __shfl_xor_sync(0xffffffffu, zq[q], o);
    }
    if (lane == 0) {
        #pragma unroll
        for (int q = 0; q < NQ; ++q) red[w][q] = zq[q];
    }
    __syncthreads();
    if (t < NQ)
        out[s * NQ + t] = red[0][t] + red[1][t];
}

extern "C" void kernel_launch(void* const* d_in, const int* in_sizes, int n_in,
                              void* d_out, int out_size) {
    const float* x = (const float*)d_in[0];
    const float* w = (const float*)d_in[1];
    float* out = (float*)d_out;
    int B = in_sizes[0] / (2 * NQ);   // 4096 flattened samples
    precompute_kernel<<<1, 128>>>(w);
    qsim_kernel<<<B, TPB>>>(x, out);
}